// round 1
// baseline (speedup 1.0000x reference)
#include <cuda_runtime.h>
#include <math.h>

#define N 8192
#define D 64
#define GAT_ALPHA 0.2f

// ---------------- scratch (device globals; no allocation) ----------------
__device__ float  g_h[N * D];          // projected features, 2 MB
__device__ float  g_f1[N];
__device__ float  g_f2[N];
__device__ int    g_rank[N];
__device__ float  g_f2s[N];            // f2 sorted ascending
__device__ int    g_sidx[N];           // permutation: sorted pos -> original j
__device__ double g_Shot[(N + 1) * D];   // suffix sums  sum_{q>=p} e^{f2-m2} h
__device__ double g_Pcold[(N + 1) * D];  // excl prefix  sum_{q< p} e^{a(f2-m2)} h
__device__ double g_Shot_s[N + 1];       // scalar versions (normalizer)
__device__ double g_Pcold_s[N + 1];

// monotone float -> uint mapping (total order, preserves float ordering)
__device__ __forceinline__ unsigned fkey(float f) {
    unsigned u = __float_as_uint(f);
    return (u & 0x80000000u) ? ~u : (u | 0x80000000u);
}

// ---------------- k1: h = x @ Wt ; f1 = h@a1+b1 ; f2 = h@a2+b2 ----------------
__global__ void k1_proj(const float* __restrict__ x, const float* __restrict__ Wt,
                        const float* __restrict__ a1, const float* __restrict__ b1,
                        const float* __restrict__ a2, const float* __restrict__ b2) {
    __shared__ float Ws[D * D];
    __shared__ float a1s[D], a2s[D];
    __shared__ float xs[32 * D];
    __shared__ float hs[32 * D];
    int t = threadIdx.x;
    int rbase = blockIdx.x * 32;

    for (int k = t; k < D * D; k += 256) Ws[k] = Wt[k];
    if (t < D) { a1s[t] = a1[t]; a2s[t] = a2[t]; }
    for (int k = t; k < 32 * D; k += 256) xs[k] = x[rbase * D + k];

    // also zero the rank array (grid covers >= N threads)
    int gi = blockIdx.x * 256 + t;
    if (gi < N) g_rank[gi] = 0;
    __syncthreads();

    int o = t & 63;
    int r0 = t >> 6;                 // 0..3
    #pragma unroll
    for (int rr = 0; rr < 8; rr++) {
        int r = r0 + rr * 4;         // 0..31
        float acc = 0.f;
        #pragma unroll
        for (int k = 0; k < D; k++) acc = fmaf(xs[r * D + k], Ws[k * D + o], acc);
        hs[r * D + o] = acc;
        g_h[(rbase + r) * D + o] = acc;
    }
    __syncthreads();

    int w = t >> 5, lane = t & 31;
    float bb1 = b1[0], bb2 = b2[0];
    #pragma unroll
    for (int rr = 0; rr < 4; rr++) {
        int r = w + rr * 8;          // 0..31
        float h0 = hs[r * D + lane], h1 = hs[r * D + lane + 32];
        float v1 = h0 * a1s[lane] + h1 * a1s[lane + 32];
        float v2 = h0 * a2s[lane] + h1 * a2s[lane + 32];
        #pragma unroll
        for (int off = 16; off > 0; off >>= 1) {
            v1 += __shfl_down_sync(0xffffffffu, v1, off);
            v2 += __shfl_down_sync(0xffffffffu, v2, off);
        }
        if (lane == 0) {
            g_f1[rbase + r] = v1 + bb1;
            g_f2[rbase + r] = v2 + bb2;
        }
    }
}

// ---------------- k2: exact rank of each f2 (tiled counting sort) ----------------
__global__ void k2_rank() {
    __shared__ unsigned sk[256];
    int t = threadIdx.x;
    int ib = blockIdx.x * 256, kb = blockIdx.y * 256;
    sk[t] = fkey(g_f2[kb + t]);
    __syncthreads();
    int i = ib + t;
    unsigned ki = fkey(g_f2[i]);
    int cnt = 0;
    #pragma unroll 8
    for (int s = 0; s < 256; s++) {
        unsigned ks = sk[s];
        cnt += (ks < ki) || (ks == ki && (kb + s) < i);
    }
    atomicAdd(&g_rank[i], cnt);
}

__global__ void k2b_scatter() {
    int j = blockIdx.x * 256 + threadIdx.x;
    if (j < N) {
        int p = g_rank[j];
        g_f2s[p] = g_f2[j];
        g_sidx[p] = j;
    }
}

// ---------------- k3: suffix (hot) / exclusive-prefix (cold) scans ----------------
// grid: (D+1, 2). blockIdx.x = column (D == scalar col). blockIdx.y: 0=hot,1=cold.
__global__ void k3_scan() {
    __shared__ double s[256];
    int t = threadIdx.x;
    int col = blockIdx.x;
    int hot = (blockIdx.y == 0);
    float m2 = g_f2s[N - 1];
    double carry = 0.0;

    for (int chunk = 0; chunk < N / 256; chunk++) {
        int pos = chunk * 256 + t;
        int q = hot ? (N - 1 - pos) : pos;
        float f2v = g_f2s[q];
        float e = hot ? expf(f2v - m2) : expf(GAT_ALPHA * (f2v - m2));
        double val = (col < D) ? (double)e * (double)g_h[g_sidx[q] * D + col]
                               : (double)e;
        s[t] = val;
        __syncthreads();
        #pragma unroll
        for (int off = 1; off < 256; off <<= 1) {
            double add = (t >= off) ? s[t - off] : 0.0;
            __syncthreads();
            s[t] += add;
            __syncthreads();
        }
        double incl = s[t];
        double total = s[255];
        if (hot) {
            double Sq = carry + incl;            // inclusive suffix at q
            if (col < D) g_Shot[q * D + col] = Sq; else g_Shot_s[q] = Sq;
        } else {
            double Pq = carry + incl - val;      // exclusive prefix at q
            if (col < D) g_Pcold[q * D + col] = Pq; else g_Pcold_s[q] = Pq;
        }
        carry += total;
        __syncthreads();                          // protect s[] before next chunk
    }
    if (t == 0) {
        if (hot) { if (col < D) g_Shot[N * D + col] = 0.0; else g_Shot_s[N] = 0.0; }
        else     { if (col < D) g_Pcold[N * D + col] = carry; else g_Pcold_s[N] = carry; }
    }
}

// ---------------- k4: per-row combine + ELU ----------------
__global__ void k4_out(float* __restrict__ out) {
    int i = (blockIdx.x * blockDim.x + threadIdx.x) >> 5;   // warp per row
    int lane = threadIdx.x & 31;
    if (i >= N) return;

    float t1 = g_f1[i];
    float theta = -t1;
    float m2 = g_f2s[N - 1];

    // lower_bound: first p with f2s[p] >= theta  (hot set = [p, N))
    int lo = 0, hi = N;
    while (lo < hi) {
        int mid = (lo + hi) >> 1;
        if (g_f2s[mid] < theta) lo = mid + 1; else hi = mid;
    }
    int p = lo;

    float z = t1 + m2;
    float c = (z >= 0.f) ? z : GAT_ALPHA * z;     // row max of leaky logits
    double sh = exp((double)z - (double)c);        // e^{f1 + m2 - c}
    double sc = exp((double)(GAT_ALPHA * z) - (double)c);

    double denom = sh * g_Shot_s[p] + sc * g_Pcold_s[p];

    #pragma unroll
    for (int dd = 0; dd < 2; dd++) {
        int d = lane + dd * 32;
        double num = sh * g_Shot[p * D + d] + sc * g_Pcold[p * D + d];
        float v = (float)(num / denom);
        out[i * D + d] = (v > 0.f) ? v : expm1f(v);   // ELU(alpha=1)
    }
}

// ---------------- launch ----------------
extern "C" void kernel_launch(void* const* d_in, const int* in_sizes, int n_in,
                              void* d_out, int out_size) {
    const float* x  = (const float*)d_in[0];
    const float* Wt = (const float*)d_in[1];
    const float* a1 = (const float*)d_in[2];
    const float* b1 = (const float*)d_in[3];
    const float* a2 = (const float*)d_in[4];
    const float* b2 = (const float*)d_in[5];
    float* out = (float*)d_out;

    k1_proj<<<N / 32, 256>>>(x, Wt, a1, b1, a2, b2);
    k2_rank<<<dim3(N / 256, N / 256), 256>>>();
    k2b_scatter<<<N / 256, 256>>>();
    k3_scan<<<dim3(D + 1, 2), 256>>>();
    k4_out<<<N / 8, 256>>>(out);
}

// round 2
// speedup vs baseline: 1.6828x; 1.6828x over previous
#include <cuda_runtime.h>
#include <math.h>

#define N 8192
#define D 64
#define GAT_ALPHA 0.2f
#define NB 4096

// ---------------- scratch (device globals; no allocation) ----------------
__device__ float  g_h[N * D];          // projected features (row-major)
__device__ float  g_f1[N];
__device__ float  g_f2[N];
__device__ int    g_hist[NB];
__device__ int    g_hist2[NB];
__device__ int    g_binoff[NB + 1];
__device__ unsigned long long g_bkt[N];  // (fkey<<32)|idx grouped by bucket
__device__ float  g_f2s[N];            // f2 sorted ascending
__device__ int    g_sidx[N];           // sorted pos -> original j
__device__ float  g_hcm[D * N];        // column-major permuted h: [d][p]
__device__ float  g_ehot[N];           // exp(f2s - m2)
__device__ float  g_ecold[N];          // exp(alpha*(f2s - m2))
__device__ double g_Shot[(N + 1) * D];   // inclusive suffix sums (hot)
__device__ double g_Pcold[(N + 1) * D];  // exclusive prefix sums (cold)
__device__ double g_Shot_s[N + 1];
__device__ double g_Pcold_s[N + 1];

// monotone float -> uint mapping (preserves float ordering)
__device__ __forceinline__ unsigned fkey(float f) {
    unsigned u = __float_as_uint(f);
    return (u & 0x80000000u) ? ~u : (u | 0x80000000u);
}
__device__ __forceinline__ float unfkey(unsigned k) {
    unsigned u = (k & 0x80000000u) ? (k & 0x7fffffffu) : ~k;
    return __uint_as_float(u);
}

// ---------------- k1: h = x @ Wt ; f1 = h@a1+b1 ; f2 = h@a2+b2 ----------------
__global__ void k1_proj(const float* __restrict__ x, const float* __restrict__ Wt,
                        const float* __restrict__ a1, const float* __restrict__ b1,
                        const float* __restrict__ a2, const float* __restrict__ b2) {
    __shared__ float Ws[D * D];
    __shared__ float a1s[D], a2s[D];
    __shared__ float xs[32 * D];
    __shared__ float hs[32 * D];
    int t = threadIdx.x;
    int rbase = blockIdx.x * 32;

    for (int k = t; k < D * D; k += 256) Ws[k] = Wt[k];
    if (t < D) { a1s[t] = a1[t]; a2s[t] = a2[t]; }
    for (int k = t; k < 32 * D; k += 256) xs[k] = x[rbase * D + k];

    // zero histogram arrays (grid has 65536 threads, need 2*NB=8192)
    int gi = blockIdx.x * 256 + t;
    if (gi < NB) g_hist[gi] = 0;
    else if (gi < 2 * NB) g_hist2[gi - NB] = 0;
    __syncthreads();

    int o = t & 63;
    int r0 = t >> 6;                 // 0..3
    #pragma unroll
    for (int rr = 0; rr < 8; rr++) {
        int r = r0 + rr * 4;         // 0..31
        float acc = 0.f;
        #pragma unroll
        for (int k = 0; k < D; k++) acc = fmaf(xs[r * D + k], Ws[k * D + o], acc);
        hs[r * D + o] = acc;
        g_h[(rbase + r) * D + o] = acc;
    }
    __syncthreads();

    int w = t >> 5, lane = t & 31;
    float bb1 = b1[0], bb2 = b2[0];
    #pragma unroll
    for (int rr = 0; rr < 4; rr++) {
        int r = w + rr * 8;          // 0..31
        float h0 = hs[r * D + lane], h1 = hs[r * D + lane + 32];
        float v1 = h0 * a1s[lane] + h1 * a1s[lane + 32];
        float v2 = h0 * a2s[lane] + h1 * a2s[lane + 32];
        #pragma unroll
        for (int off = 16; off > 0; off >>= 1) {
            v1 += __shfl_down_sync(0xffffffffu, v1, off);
            v2 += __shfl_down_sync(0xffffffffu, v2, off);
        }
        if (lane == 0) {
            g_f1[rbase + r] = v1 + bb1;
            g_f2[rbase + r] = v2 + bb2;
        }
    }
}

// ---------------- k2: bucketed exact sort of f2 ----------------
__global__ void k2a_hist() {
    int j = blockIdx.x * 256 + threadIdx.x;
    unsigned k = fkey(g_f2[j]);
    atomicAdd(&g_hist[k >> 20], 1);
}

__global__ void k2b_binscan() {   // 1 block, 1024 threads, NB=4096 bins
    __shared__ int sc[1024];
    int t = threadIdx.x;
    int c0 = g_hist[4 * t], c1 = g_hist[4 * t + 1];
    int c2 = g_hist[4 * t + 2], c3 = g_hist[4 * t + 3];
    int T = c0 + c1 + c2 + c3;
    sc[t] = T;
    __syncthreads();
    #pragma unroll
    for (int off = 1; off < 1024; off <<= 1) {
        int add = (t >= off) ? sc[t - off] : 0;
        __syncthreads();
        sc[t] += add;
        __syncthreads();
    }
    int excl = sc[t] - T;
    g_binoff[4 * t] = excl;
    g_binoff[4 * t + 1] = excl + c0;
    g_binoff[4 * t + 2] = excl + c0 + c1;
    g_binoff[4 * t + 3] = excl + c0 + c1 + c2;
    if (t == 1023) g_binoff[NB] = excl + T;   // == N
}

__global__ void k2c_scatter() {
    int j = blockIdx.x * 256 + threadIdx.x;
    unsigned k = fkey(g_f2[j]);
    int b = k >> 20;
    int pos = g_binoff[b] + atomicAdd(&g_hist2[b], 1);
    g_bkt[pos] = ((unsigned long long)k << 32) | (unsigned)j;
}

__global__ void k2d_rank() {
    int pos = blockIdx.x * 256 + threadIdx.x;
    unsigned long long me = g_bkt[pos];
    unsigned k = (unsigned)(me >> 32);
    int b = k >> 20;
    int lo = g_binoff[b], hi = g_binoff[b + 1];
    int cnt = 0;
    for (int q = lo; q < hi; q++) cnt += (g_bkt[q] < me) ? 1 : 0;
    int r = lo + cnt;
    g_f2s[r] = unfkey(k);
    g_sidx[r] = (int)(me & 0xffffffffu);
}

// ---------------- k3a: gather-transpose h by sorted order + exp weights ----------------
__global__ void k3a_prep() {
    __shared__ float tile[64][65];
    int t = threadIdx.x;
    int p0 = blockIdx.x * 64;
    int c = t & 63, r4 = t >> 6;
    #pragma unroll
    for (int rr = 0; rr < 16; rr++) {
        int r = rr * 4 + r4;
        tile[r][c] = g_h[g_sidx[p0 + r] * D + c];
    }
    if (t < 64) {
        float m2 = g_f2s[N - 1];
        float f = g_f2s[p0 + t];
        g_ehot[p0 + t]  = expf(f - m2);
        g_ecold[p0 + t] = expf(GAT_ALPHA * (f - m2));
    }
    __syncthreads();
    #pragma unroll
    for (int rr = 0; rr < 16; rr++) {
        int d = rr * 4 + r4;
        g_hcm[d * N + p0 + c] = tile[c][d];
    }
}

// ---------------- k3: work-efficient suffix(hot)/prefix(cold) scans ----------------
// grid (D+1, 2): blockIdx.x = column (D == scalar normalizer), y: 0=hot, 1=cold
__global__ void k3_scan() {
    __shared__ double sc[256];
    int t = threadIdx.x;
    int col = blockIdx.x;
    int hot = (blockIdx.y == 0);
    const float* e = hot ? g_ehot : g_ecold;

    // this thread owns ascending-q range [base, base+32)
    int base = hot ? (N - 32 - t * 32) : (t * 32);
    float w[32];
    const float4* e4 = (const float4*)(e + base);
    if (col < D) {
        const float4* h4 = (const float4*)(g_hcm + col * N + base);
        #pragma unroll
        for (int k = 0; k < 8; k++) {
            float4 hv = h4[k], ev = e4[k];
            w[4 * k + 0] = hv.x * ev.x; w[4 * k + 1] = hv.y * ev.y;
            w[4 * k + 2] = hv.z * ev.z; w[4 * k + 3] = hv.w * ev.w;
        }
    } else {
        #pragma unroll
        for (int k = 0; k < 8; k++) {
            float4 ev = e4[k];
            w[4 * k + 0] = ev.x; w[4 * k + 1] = ev.y;
            w[4 * k + 2] = ev.z; w[4 * k + 3] = ev.w;
        }
    }

    double T = 0.0;
    #pragma unroll
    for (int i = 0; i < 32; i++) T += (double)w[i];
    sc[t] = T;
    __syncthreads();
    #pragma unroll
    for (int off = 1; off < 256; off <<= 1) {
        double add = (t >= off) ? sc[t - off] : 0.0;
        __syncthreads();
        sc[t] += add;
        __syncthreads();
    }
    double run = sc[t] - T;   // exclusive offset in scan order

    if (hot) {
        // scan order visits q descending: i-th element is q = base+31-i, weight w[31-i]
        if (col < D) {
            #pragma unroll
            for (int i = 0; i < 32; i++) {
                run += (double)w[31 - i];
                g_Shot[(base + 31 - i) * D + col] = run;   // inclusive suffix
            }
        } else {
            #pragma unroll
            for (int i = 0; i < 32; i++) {
                run += (double)w[31 - i];
                g_Shot_s[base + 31 - i] = run;
            }
        }
        if (t == 0) { if (col < D) g_Shot[N * D + col] = 0.0; else g_Shot_s[N] = 0.0; }
    } else {
        if (col < D) {
            #pragma unroll
            for (int i = 0; i < 32; i++) {
                g_Pcold[(base + i) * D + col] = run;       // exclusive prefix
                run += (double)w[i];
            }
        } else {
            #pragma unroll
            for (int i = 0; i < 32; i++) {
                g_Pcold_s[base + i] = run;
                run += (double)w[i];
            }
        }
        if (t == 255) {
            double tot = sc[255];
            if (col < D) g_Pcold[N * D + col] = tot; else g_Pcold_s[N] = tot;
        }
    }
}

// ---------------- k4: per-row combine + ELU ----------------
__global__ void k4_out(float* __restrict__ out) {
    int i = (blockIdx.x * blockDim.x + threadIdx.x) >> 5;   // warp per row
    int lane = threadIdx.x & 31;
    if (i >= N) return;

    float t1 = g_f1[i];
    float theta = -t1;
    float m2 = g_f2s[N - 1];

    // lower_bound: first p with f2s[p] >= theta  (hot set = [p, N))
    int lo = 0, hi = N;
    while (lo < hi) {
        int mid = (lo + hi) >> 1;
        if (g_f2s[mid] < theta) lo = mid + 1; else hi = mid;
    }
    int p = lo;

    float z = t1 + m2;
    float c = (z >= 0.f) ? z : GAT_ALPHA * z;     // row max of leaky logits
    double sh = exp((double)z - (double)c);
    double sc = exp((double)(GAT_ALPHA * z) - (double)c);

    double denom = sh * g_Shot_s[p] + sc * g_Pcold_s[p];

    #pragma unroll
    for (int dd = 0; dd < 2; dd++) {
        int d = lane + dd * 32;
        double num = sh * g_Shot[p * D + d] + sc * g_Pcold[p * D + d];
        float v = (float)(num / denom);
        out[i * D + d] = (v > 0.f) ? v : expm1f(v);   // ELU(alpha=1)
    }
}

// ---------------- launch ----------------
extern "C" void kernel_launch(void* const* d_in, const int* in_sizes, int n_in,
                              void* d_out, int out_size) {
    const float* x  = (const float*)d_in[0];
    const float* Wt = (const float*)d_in[1];
    const float* a1 = (const float*)d_in[2];
    const float* b1 = (const float*)d_in[3];
    const float* a2 = (const float*)d_in[4];
    const float* b2 = (const float*)d_in[5];
    float* out = (float*)d_out;

    k1_proj<<<N / 32, 256>>>(x, Wt, a1, b1, a2, b2);
    k2a_hist<<<N / 256, 256>>>();
    k2b_binscan<<<1, 1024>>>();
    k2c_scatter<<<N / 256, 256>>>();
    k2d_rank<<<N / 256, 256>>>();
    k3a_prep<<<N / 64, 256>>>();
    k3_scan<<<dim3(D + 1, 2), 256>>>();
    k4_out<<<N / 8, 256>>>(out);
}